// round 6
// baseline (speedup 1.0000x reference)
#include <cuda_runtime.h>
#include <cuda_bf16.h>
#include <cstdint>

#define N_PTS 400000
#define DIM   128
#define KNB   27
#define NSEG  8
#define MTILE 128
#define CTHR  512
#define NTHR  256
#define NBLK  (N_PTS / MTILE)
#define FTILE 64

// ---------------- scratch (static device globals: allocation-free) ----------------
__device__ float g_out1[(size_t)N_PTS * DIM];
__device__ float g_out2[(size_t)N_PTS * DIM];
__device__ float g_segsum[NSEG * DIM];
__device__ float g_segmean[NSEG * DIM];
__device__ int   g_segcnt[NSEG];
__device__ unsigned int g_amaxf;
__device__ unsigned int g_wamax[2];
__device__ signed char g_q1[(size_t)N_PTS * DIM];   // feats level-1 int8
__device__ signed char g_q2[(size_t)N_PTS * DIM];   // feats level-2 int8
// W images: [k][conv][level] 16KB int8 tiles (row n = 128 k-bytes, swizzled chunks)
__device__ signed char g_Wq[(size_t)KNB * 2 * 2 * 16384];

// ---------------- smem layout for conv kernel (bytes) ----------------
#define SM_MB   0                                // 2 mbars @0,@8
#define SM_IDX  64
#define SM_MSK  (SM_IDX + MTILE * KNB * 4)       // 13888
#define SM_A    17408                            // [buf][part] 4 x 16KB
#define SM_W    (SM_A + 65536)                   // [buf][level] 4 x 16KB  -> 82944
#define SM_TOTAL (SM_W + 65536)                  // 148480

__device__ __forceinline__ uint32_t smem_u32(const void* p) {
    return (uint32_t)__cvta_generic_to_shared(p);
}

// ---------------- PTX helpers ----------------
#define MBAR_INIT(a, c) \
    asm volatile("mbarrier.init.shared.b64 [%0], %1;" :: "r"(a), "r"(c) : "memory")
#define MBAR_EXPECT_TX(a, b) \
    asm volatile("mbarrier.arrive.expect_tx.shared.b64 _, [%0], %1;" :: "r"(a), "r"(b) : "memory")
#define MBAR_WAIT(a, ph) do {                                                 \
    uint32_t _m = (a), _p = (ph), _d;                                         \
    asm volatile("{\n .reg .pred p;\n"                                        \
        " mbarrier.try_wait.parity.acquire.cta.shared::cta.b64 p, [%1], %2;\n"\
        " selp.b32 %0, 1, 0, p;\n}" : "=r"(_d) : "r"(_m), "r"(_p) : "memory");\
    if (!_d) {                                                                \
        asm volatile("{\n .reg .pred P1;\n"                                   \
        "W%=:\n mbarrier.try_wait.parity.acquire.cta.shared::cta.b64 P1, [%0], %1, 0x989680;\n" \
        " @P1 bra.uni D%=;\n bra.uni W%=;\nD%=:\n}" :: "r"(_m), "r"(_p) : "memory"); \
    } } while (0)

#define CP_COMMIT() asm volatile("cp.async.commit_group;" ::: "memory")
#define CP_WAIT(n)  asm volatile("cp.async.wait_group %0;" :: "n"(n) : "memory")

__device__ __forceinline__ void cp16z(uint32_t dst, const void* src, uint32_t srcsz) {
    asm volatile("cp.async.cg.shared.global [%0], [%1], 16, %2;"
                 :: "r"(dst), "l"(src), "r"(srcsz) : "memory");
}
__device__ __forceinline__ void bulk_g2s(uint32_t dst, const void* src,
                                         uint32_t bytes, uint32_t mbar) {
    asm volatile(
        "cp.async.bulk.shared::cluster.global.mbarrier::complete_tx::bytes "
        "[%0], [%1], %2, [%3];"
        :: "r"(dst), "l"(src), "r"(bytes), "r"(mbar) : "memory");
}
__device__ __forceinline__ void ldsm4(uint32_t* r, uint32_t addr) {
    asm volatile("ldmatrix.sync.aligned.m8n8.x4.shared.b16 {%0,%1,%2,%3}, [%4];"
        : "=r"(r[0]), "=r"(r[1]), "=r"(r[2]), "=r"(r[3]) : "r"(addr));
}
// int8 MMA, s32 accumulate (exact)
__device__ __forceinline__ void imma8(int* c, const uint32_t* a, const uint32_t* b) {
    asm volatile("mma.sync.aligned.m16n8k32.row.col.s32.s8.s8.s32 "
        "{%0,%1,%2,%3}, {%4,%5,%6,%7}, {%8,%9}, {%0,%1,%2,%3};"
        : "+r"(c[0]), "+r"(c[1]), "+r"(c[2]), "+r"(c[3])
        : "r"(a[0]), "r"(a[1]), "r"(a[2]), "r"(a[3]), "r"(b[0]), "r"(b[1]));
}

// ---------------- packed f32x2 helpers (finalize FFMA2 GEMM) ----------
__device__ __forceinline__ void fma2(unsigned long long& d, unsigned long long a,
                                     unsigned long long b) {
    asm("fma.rn.f32x2 %0, %1, %2, %0;" : "+l"(d) : "l"(a), "l"(b));
}
__device__ __forceinline__ unsigned long long dup2(float x) {
    unsigned long long r;
    asm("mov.b64 %0, {%1, %1};" : "=l"(r) : "f"(x));
    return r;
}
__device__ __forceinline__ float2 upk(unsigned long long v) {
    float2 r;
    asm("mov.b64 {%0, %1}, %2;" : "=f"(r.x), "=f"(r.y) : "l"(v));
    return r;
}

// ---------------- zero accumulators / amax (graph replays!) ----------------
__global__ void zero_seg_kernel() {
    int t = blockIdx.x * blockDim.x + threadIdx.x;
    if (t < NSEG * DIM) g_segsum[t] = 0.f;
    if (t < NSEG) g_segcnt[t] = 0;
    if (t == 0) g_amaxf = 0u;
    if (t == 1) g_wamax[0] = 0u;
    if (t == 2) g_wamax[1] = 0u;
}

// ---------------- amax reductions ----------------
__global__ void amax_feats_kernel(const float* __restrict__ f) {
    const size_t stride = (size_t)gridDim.x * blockDim.x * 4;
    size_t i = ((size_t)blockIdx.x * blockDim.x + threadIdx.x) * 4;
    float m = 0.f;
    for (; i < (size_t)N_PTS * DIM; i += stride) {
        const float4 v = *reinterpret_cast<const float4*>(f + i);
        m = fmaxf(m, fmaxf(fmaxf(fabsf(v.x), fabsf(v.y)), fmaxf(fabsf(v.z), fabsf(v.w))));
    }
#pragma unroll
    for (int o = 16; o; o >>= 1) m = fmaxf(m, __shfl_xor_sync(~0u, m, o));
    if ((threadIdx.x & 31) == 0) atomicMax(&g_amaxf, __float_as_uint(m));
}
__global__ void amax_w_kernel(const float* __restrict__ W1, const float* __restrict__ W2) {
    const float* W = blockIdx.y ? W2 : W1;
    const int total = KNB * DIM * DIM;
    const int stride = gridDim.x * blockDim.x * 4;
    int i = (blockIdx.x * blockDim.x + threadIdx.x) * 4;
    float m = 0.f;
    for (; i < total; i += stride) {
        const float4 v = *reinterpret_cast<const float4*>(W + i);
        m = fmaxf(m, fmaxf(fmaxf(fabsf(v.x), fabsf(v.y)), fmaxf(fabsf(v.z), fabsf(v.w))));
    }
#pragma unroll
    for (int o = 16; o; o >>= 1) m = fmaxf(m, __shfl_xor_sync(~0u, m, o));
    if ((threadIdx.x & 31) == 0) atomicMax(&g_wamax[blockIdx.y], __float_as_uint(m));
}

// ---------------- quantize feats: two-level int8 ----------------
__device__ __forceinline__ int q8(float x) {
    int q = __float2int_rn(x);
    return max(-127, min(127, q));
}
__global__ void quant_feats_kernel(const float* __restrict__ feats) {
    const size_t i = ((size_t)blockIdx.x * NTHR + threadIdx.x) * 4;
    const float amax = fmaxf(__uint_as_float(g_amaxf), 1e-20f);
    const float s1 = amax * (1.f / 127.f);
    const float inv_s1 = 127.f / amax;
    const float inv_s2 = inv_s1 * 254.f;
    const float s2 = s1 * (1.f / 254.f);
    const float4 v = *reinterpret_cast<const float4*>(feats + i);
    int ax = q8(v.x * inv_s1), ay = q8(v.y * inv_s1),
        az = q8(v.z * inv_s1), aw = q8(v.w * inv_s1);
    float rx = fmaf(-s1, (float)ax, v.x), ry = fmaf(-s1, (float)ay, v.y);
    float rz = fmaf(-s1, (float)az, v.z), rw = fmaf(-s1, (float)aw, v.w);
    int bx = q8(rx * inv_s2), by = q8(ry * inv_s2),
        bz = q8(rz * inv_s2), bw = q8(rw * inv_s2);
    (void)s2;
    uint32_t p1 = (uint32_t)(ax & 255) | ((uint32_t)(ay & 255) << 8) |
                  ((uint32_t)(az & 255) << 16) | ((uint32_t)(aw & 255) << 24);
    uint32_t p2 = (uint32_t)(bx & 255) | ((uint32_t)(by & 255) << 8) |
                  ((uint32_t)(bz & 255) << 16) | ((uint32_t)(bw & 255) << 24);
    *reinterpret_cast<uint32_t*>(g_q1 + i) = p1;
    *reinterpret_cast<uint32_t*>(g_q2 + i) = p2;
}

// ---------------- W -> transposed two-level int8 SMEM-image ----------------
__global__ void prep_w_kernel(const float* __restrict__ W1, const float* __restrict__ W2) {
    const uint32_t t = blockIdx.x * NTHR + threadIdx.x;   // 27*2*128*128 threads
    const uint32_t d = t & 127;
    const uint32_t n = (t >> 7) & 127;
    const uint32_t conv = (t >> 14) & 1;
    const uint32_t k = t >> 15;
    const float amax = fmaxf(__uint_as_float(g_wamax[conv]), 1e-20f);
    const float t1 = amax * (1.f / 127.f);
    const float inv_t1 = 127.f / amax;
    const float inv_t2 = inv_t1 * 254.f;
    const float w = (conv ? W2 : W1)[((size_t)k * DIM + d) * DIM + n];
    const int p1 = q8(w * inv_t1);
    const float u = fmaf(-t1, (float)p1, w);
    const int p2 = q8(u * inv_t2);
    // image: row n = 128 bytes over d; 16B chunk c stored at chunk (c ^ (n&7))
    const uint32_t off = n * 128 + (((d >> 4) ^ (n & 7)) << 4) + (d & 15);
    signed char* base = g_Wq + (size_t)k * 65536 + (size_t)conv * 32768;
    base[off] = (signed char)p1;
    base[16384 + off] = (signed char)p2;
}

// ---------------- A staging via cp.async zfill (both int8 parts) ----------
__device__ __forceinline__ void stage_A(uint32_t sb, uint32_t buf,
                                        const int* idx_s,
                                        const unsigned char* msk_s, int k) {
    const int t = threadIdx.x;
    const int r = t >> 2;                  // row 0..127
    const int q = t & 3;                   // 2 chunks per thread per part
    const int id = idx_s[r * KNB + k];
    const uint32_t sz = msk_s[r * KNB + k] ? 16u : 0u;
    const uint32_t x = (uint32_t)(r & 7);
    const uint32_t drow = sb + SM_A + buf * 32768 + (uint32_t)r * 128;
    const char* s1p = reinterpret_cast<const char*>(g_q1) + (size_t)id * 128 + q * 32;
    const char* s2p = reinterpret_cast<const char*>(g_q2) + (size_t)id * 128 + q * 32;
#pragma unroll
    for (int c2 = 0; c2 < 2; c2++) {
        const uint32_t c = (uint32_t)(q * 2 + c2);
        cp16z(drow + ((c ^ x) << 4), s1p + c2 * 16, sz);
        cp16z(drow + 16384 + ((c ^ x) << 4), s2p + c2 * 16, sz);
    }
}

// ---------------- int8 conv kernel: one conv per CTA, double-buffered ----------
__global__ void __launch_bounds__(CTHR, 1)
conv_imma_kernel(const int* __restrict__ nidx, const int* __restrict__ nmask,
                 const float* __restrict__ b1, const float* __restrict__ b2) {
    extern __shared__ char smem[];
    const uint32_t sb = smem_u32(smem);
    const int t = threadIdx.x;
    const int lane = t & 31;
    const int wid = t >> 5;
    const int wm = wid >> 2;        // 0..3 : 32-row band
    const int wn = wid & 3;         // 0..3 : 32-col band
    const int conv = blockIdx.y;
    const int nbase = blockIdx.x * MTILE;

    int* idx_s = reinterpret_cast<int*>(smem + SM_IDX);
    unsigned char* msk_s = reinterpret_cast<unsigned char*>(smem + SM_MSK);

    for (int i = t; i < MTILE * KNB; i += CTHR) {
        idx_s[i] = nidx[(size_t)nbase * KNB + i];
        msk_s[i] = (unsigned char)(nmask[(size_t)nbase * KNB + i] != 0);
    }
    const char* wimg = reinterpret_cast<const char*>(g_Wq) + (size_t)conv * 32768;
    if (t == 0) {
        MBAR_INIT(sb + SM_MB, 1);
        MBAR_INIT(sb + SM_MB + 8, 1);
        MBAR_EXPECT_TX(sb + SM_MB, 32768);
        bulk_g2s(sb + SM_W, wimg, 32768, sb + SM_MB);   // W[0] both levels
    }
    __syncthreads();          // idx/msk + mbar init visible
    stage_A(sb, 0, idx_s, msk_s, 0);
    CP_COMMIT();

    // per-thread ldmatrix address components
    const uint32_t arow0 = (uint32_t)(wm * 32 + (lane & 15));
    const uint32_t achunk = (uint32_t)(lane >> 4);
    const uint32_t wrow = (uint32_t)(wn * 32 + ((lane >> 4) << 3) + (lane & 7));
    const uint32_t wchunk = (uint32_t)((lane >> 3) & 1);

    int G1[2][4][4], G2[2][4][4], G3[2][4][4];
#pragma unroll
    for (int i = 0; i < 2; i++)
#pragma unroll
        for (int j = 0; j < 4; j++)
#pragma unroll
            for (int q = 0; q < 4; q++) { G1[i][j][q] = 0; G2[i][j][q] = 0; G3[i][j][q] = 0; }

#pragma unroll 1
    for (int k = 0; k < KNB; k++) {
        const uint32_t buf = (uint32_t)(k & 1);
        const uint32_t ph = (uint32_t)((k >> 1) & 1);
        // stage k+1 into the other buffer (its prior user finished at end of k-1)
        if (k < KNB - 1) {
            const uint32_t nb = buf ^ 1;
            if (t == 0) {
                MBAR_EXPECT_TX(sb + SM_MB + 8 * nb, 32768);
                bulk_g2s(sb + SM_W + nb * 32768, wimg + (size_t)(k + 1) * 65536,
                         32768, sb + SM_MB + 8 * nb);
            }
            stage_A(sb, nb, idx_s, msk_s, k + 1);
        }
        CP_COMMIT();               // always: keeps pending-group invariant
        CP_WAIT(1);                // A[k] complete (own threads)
        MBAR_WAIT(sb + SM_MB + 8 * buf, ph);   // W[k] complete
        __syncthreads();           // A stores visible CTA-wide

        const uint32_t aB1 = sb + SM_A + buf * 32768;          // q1 part
        const uint32_t aB2 = aB1 + 16384;                      // q2 part
        const uint32_t wB1 = sb + SM_W + buf * 32768;          // level1
        const uint32_t wB2 = wB1 + 16384;                      // level2
#pragma unroll
        for (uint32_t kc = 0; kc < 4; kc++) {
            uint32_t a1[2][4], a2[2][4], w[2][4];
            const uint32_t ach = 2 * kc + achunk;
            const uint32_t wch = 2 * kc + wchunk;
#pragma unroll
            for (uint32_t i = 0; i < 2; i++) {
                const uint32_t row = arow0 + i * 16;
                const uint32_t boff = row * 128 + (((ach) ^ (row & 7)) << 4);
                ldsm4(a1[i], aB1 + boff);
                ldsm4(a2[i], aB2 + boff);
            }
            // level-1 W: P11 (q1p1 -> G1), P21 (q2p1 -> G2)
#pragma unroll
            for (uint32_t jp = 0; jp < 2; jp++) {
                const uint32_t row = wrow + jp * 16;
                ldsm4(w[jp], wB1 + row * 128 + ((wch ^ (row & 7)) << 4));
            }
#pragma unroll
            for (int i = 0; i < 2; i++)
#pragma unroll
                for (int j = 0; j < 4; j++)
                    imma8(G1[i][j], a1[i], &w[j >> 1][(j & 1) * 2]);
#pragma unroll
            for (int i = 0; i < 2; i++)
#pragma unroll
                for (int j = 0; j < 4; j++)
                    imma8(G2[i][j], a2[i], &w[j >> 1][(j & 1) * 2]);
            // level-2 W: P12 (q1p2 -> G2), P22 (q2p2 -> G3)
#pragma unroll
            for (uint32_t jp = 0; jp < 2; jp++) {
                const uint32_t row = wrow + jp * 16;
                ldsm4(w[jp], wB2 + row * 128 + ((wch ^ (row & 7)) << 4));
            }
#pragma unroll
            for (int i = 0; i < 2; i++)
#pragma unroll
                for (int j = 0; j < 4; j++)
                    imma8(G2[i][j], a1[i], &w[j >> 1][(j & 1) * 2]);
#pragma unroll
            for (int i = 0; i < 2; i++)
#pragma unroll
                for (int j = 0; j < 4; j++)
                    imma8(G3[i][j], a2[i], &w[j >> 1][(j & 1) * 2]);
        }
        __syncthreads();           // all reads of buf done before restage at k+1
    }

    // epilogue: fold int32 groups -> fp32, +bias, relu, store
    const float amf = fmaxf(__uint_as_float(g_amaxf), 1e-20f);
    const float amw = fmaxf(__uint_as_float(g_wamax[conv]), 1e-20f);
    const float sc1 = (amf * (1.f / 127.f)) * (amw * (1.f / 127.f));
    const float sc2 = sc1 * (1.f / 254.f);
    const float sc3 = sc2 * (1.f / 254.f);
    float* outp = conv ? g_out2 : g_out1;
    const float* bias = conv ? b2 : b1;
    const int g = lane >> 2, tig = lane & 3;
#pragma unroll
    for (int j = 0; j < 4; j++) {
        const int col = wn * 32 + j * 8 + tig * 2;
        const float2 bv = *reinterpret_cast<const float2*>(bias + col);
#pragma unroll
        for (int i = 0; i < 2; i++) {
            const int row0 = nbase + wm * 32 + i * 16 + g;
            float2 v0, v1;
            v0.x = fmaf(sc3, (float)G3[i][j][0],
                   fmaf(sc2, (float)G2[i][j][0], sc1 * (float)G1[i][j][0])) + bv.x;
            v0.y = fmaf(sc3, (float)G3[i][j][1],
                   fmaf(sc2, (float)G2[i][j][1], sc1 * (float)G1[i][j][1])) + bv.y;
            v1.x = fmaf(sc3, (float)G3[i][j][2],
                   fmaf(sc2, (float)G2[i][j][2], sc1 * (float)G1[i][j][2])) + bv.x;
            v1.y = fmaf(sc3, (float)G3[i][j][3],
                   fmaf(sc2, (float)G2[i][j][3], sc1 * (float)G1[i][j][3])) + bv.y;
            v0.x = fmaxf(v0.x, 0.f); v0.y = fmaxf(v0.y, 0.f);
            v1.x = fmaxf(v1.x, 0.f); v1.y = fmaxf(v1.y, 0.f);
            *reinterpret_cast<float2*>(outp + (size_t)row0 * DIM + col) = v0;
            *reinterpret_cast<float2*>(outp + (size_t)(row0 + 8) * DIM + col) = v1;
        }
    }
}

// ---------------- segment sums of out2 (+counts); segment_ids sorted ----------
__global__ void segreduce_kernel(const int* __restrict__ segid) {
    const int RPB = 512, HALF = 256;
    const int c = threadIdx.x & 127;
    const int h = threadIdx.x >> 7;
    const int r0 = blockIdx.x * RPB + h * HALF;
    if (r0 >= N_PTS) return;
    const int r1 = min(r0 + HALF, N_PTS);

    float sum = 0.f;
    int cur = -1;
    for (int r = r0; r < r1; r++) {
        const int s = segid[r];
        if (s != cur) {
            if (cur >= 0) atomicAdd(&g_segsum[cur * DIM + c], sum);
            cur = s; sum = 0.f;
        }
        sum += g_out2[(size_t)r * DIM + c];
    }
    if (cur >= 0) atomicAdd(&g_segsum[cur * DIM + c], sum);

    if (c == 0) {
        int cnt = 0; cur = -1;
        for (int r = r0; r < r1; r++) {
            const int s = segid[r];
            if (s != cur) {
                if (cur >= 0) atomicAdd(&g_segcnt[cur], cnt);
                cur = s; cnt = 0;
            }
            cnt++;
        }
        if (cur >= 0) atomicAdd(&g_segcnt[cur], cnt);
    }
}

__global__ void segmean_kernel() {
    const int t = threadIdx.x;  // 1024 threads
    const int s = t >> 7;
    const float cnt = fmaxf((float)g_segcnt[s], 1.0f);
    g_segmean[t] = g_segsum[t] / cnt;
}

// ---------------- finalize: enc, mid, mid@W3, relu(feats - relu(.+b3)) -----------
__global__ void __launch_bounds__(NTHR, 2)
finalize_kernel(const float* __restrict__ feats, const int* __restrict__ segid,
                const float* __restrict__ W3, const float* __restrict__ b3,
                float* __restrict__ out) {
    extern __shared__ char smem_raw[];
    float* W3s  = reinterpret_cast<float*>(smem_raw);  // 128*128
    float* Mt   = W3s + DIM * DIM;                     // 128*64
    float* red  = Mt + DIM * FTILE;                    // 256
    float* rm1s = red + NTHR;                          // 64

    const int t = threadIdx.x;
    const int nbase = blockIdx.x * FTILE;
    const int gpt = t & 63, gseg = t >> 6;
    const int n = nbase + gpt;

    {   // stage W3
        const float4* Wg = reinterpret_cast<const float4*>(W3);
        float4* Ws4 = reinterpret_cast<float4*>(W3s);
#pragma unroll
        for (int i = 0; i < 16; i++) Ws4[t + i * NTHR] = Wg[t + i * NTHR];
    }

    const float4* o1p = reinterpret_cast<const float4*>(g_out1 + (size_t)n * DIM) + gseg * 8;
    const float4* o2p = reinterpret_cast<const float4*>(g_out2 + (size_t)n * DIM) + gseg * 8;

    float4 v1[8];
    float psum = 0.f;
#pragma unroll
    for (int q = 0; q < 8; q++) {
        v1[q] = o1p[q];
        psum += v1[q].x + v1[q].y + v1[q].z + v1[q].w;
    }
    red[t] = psum;
    __syncthreads();
    if (t < FTILE)
        rm1s[t] = (red[t] + red[t + 64] + red[t + 128] + red[t + 192]) * (1.0f / 128.0f);
    __syncthreads();

    const float rm = rm1s[gpt];
    const int sg = segid[n];
    const float4* smn = reinterpret_cast<const float4*>(g_segmean + sg * DIM) + gseg * 8;
#pragma unroll
    for (int q = 0; q < 8; q++) {
        const float4 b = o2p[q];
        const float4 m = smn[q];
        const int d0 = gseg * 32 + q * 4;
        Mt[(d0 + 0) * FTILE + gpt] = sqrtf(fmaf(rm, m.x, 1e-12f)) + v1[q].x + b.x;
        Mt[(d0 + 1) * FTILE + gpt] = sqrtf(fmaf(rm, m.y, 1e-12f)) + v1[q].y + b.y;
        Mt[(d0 + 2) * FTILE + gpt] = sqrtf(fmaf(rm, m.z, 1e-12f)) + v1[q].z + b.z;
        Mt[(d0 + 3) * FTILE + gpt] = sqrtf(fmaf(rm, m.w, 1e-12f)) + v1[q].w + b.w;
    }
    __syncthreads();

    const int cx = t & 15, py = t >> 4;
    unsigned long long acc[4][4];
#pragma unroll
    for (int i = 0; i < 4; i++)
#pragma unroll
        for (int j = 0; j < 4; j++) acc[i][j] = 0ULL;

#pragma unroll 4
    for (int d = 0; d < DIM; d++) {
        const float4 g = *reinterpret_cast<const float4*>(&Mt[d * FTILE + 4 * py]);
        const ulonglong2 w0 = *reinterpret_cast<const ulonglong2*>(&W3s[d * DIM + 8 * cx]);
        const ulonglong2 w1 = *reinterpret_cast<const ulonglong2*>(&W3s[d * DIM + 8 * cx + 4]);
        const unsigned long long ga = dup2(g.x), gb = dup2(g.y),
                                 gc = dup2(g.z), gd = dup2(g.w);
        fma2(acc[0][0], ga, w0.x); fma2(acc[0][1], ga, w0.y);
        fma2(acc[0][2], ga, w1.x); fma2(acc[0][3], ga, w1.y);
        fma2(acc[1][0], gb, w0.x); fma2(acc[1][1], gb, w0.y);
        fma2(acc[1][2], gb, w1.x); fma2(acc[1][3], gb, w1.y);
        fma2(acc[2][0], gc, w0.x); fma2(acc[2][1], gc, w0.y);
        fma2(acc[2][2], gc, w1.x); fma2(acc[2][3], gc, w1.y);
        fma2(acc[3][0], gd, w0.x); fma2(acc[3][1], gd, w0.y);
        fma2(acc[3][2], gd, w1.x); fma2(acc[3][3], gd, w1.y);
    }

    const float4 bA = *reinterpret_cast<const float4*>(&b3[8 * cx]);
    const float4 bB = *reinterpret_cast<const float4*>(&b3[8 * cx + 4]);
#pragma unroll
    for (int i = 0; i < 4; i++) {
        const int row = nbase + 4 * py + i;
        const float* fp = feats + (size_t)row * DIM + 8 * cx;
        const float4 f0 = *reinterpret_cast<const float4*>(fp);
        const float4 f1 = *reinterpret_cast<const float4*>(fp + 4);
        const float2 a0 = upk(acc[i][0]), a1 = upk(acc[i][1]);
        const float2 a2 = upk(acc[i][2]), a3 = upk(acc[i][3]);
        float4 r0, r1;
        r0.x = fmaxf(f0.x - fmaxf(a0.x + bA.x, 0.f), 0.f);
        r0.y = fmaxf(f0.y - fmaxf(a0.y + bA.y, 0.f), 0.f);
        r0.z = fmaxf(f0.z - fmaxf(a1.x + bA.z, 0.f), 0.f);
        r0.w = fmaxf(f0.w - fmaxf(a1.y + bA.w, 0.f), 0.f);
        r1.x = fmaxf(f1.x - fmaxf(a2.x + bB.x, 0.f), 0.f);
        r1.y = fmaxf(f1.y - fmaxf(a2.y + bB.y, 0.f), 0.f);
        r1.z = fmaxf(f1.z - fmaxf(a3.x + bB.z, 0.f), 0.f);
        r1.w = fmaxf(f1.w - fmaxf(a3.y + bB.w, 0.f), 0.f);
        float* op = out + (size_t)row * DIM + 8 * cx;
        *reinterpret_cast<float4*>(op)     = r0;
        *reinterpret_cast<float4*>(op + 4) = r1;
    }
}

// ---------------- launch ----------------
extern "C" void kernel_launch(void* const* d_in, const int* in_sizes, int n_in,
                              void* d_out, int out_size) {
    const float* feats = (const float*)d_in[0];
    const int* nidx = (const int*)d_in[1];
    const int* nmask = (const int*)d_in[2];   // bool materialized as int32
    const int* segid = (const int*)d_in[3];
    const int o = (n_in >= 11) ? 1 : 0;
    const float* W1 = (const float*)d_in[4 + o];
    const float* b1 = (const float*)d_in[5 + o];
    const float* W2 = (const float*)d_in[6 + o];
    const float* b2 = (const float*)d_in[7 + o];
    const float* W3 = (const float*)d_in[8 + o];
    const float* b3 = (const float*)d_in[9 + o];
    float* out = (float*)d_out;

    const size_t smem_fin = (size_t)(DIM * DIM + DIM * FTILE + NTHR + FTILE) * 4;

    cudaFuncSetAttribute(conv_imma_kernel, cudaFuncAttributeMaxDynamicSharedMemorySize,
                         SM_TOTAL);
    cudaFuncSetAttribute(finalize_kernel, cudaFuncAttributeMaxDynamicSharedMemorySize,
                         (int)smem_fin);

    zero_seg_kernel<<<1, 1024>>>();
    amax_feats_kernel<<<512, 256>>>(feats);
    {
        dim3 g(64, 2, 1);
        amax_w_kernel<<<g, 256>>>(W1, W2);
    }
    quant_feats_kernel<<<(N_PTS * DIM) / (NTHR * 4), NTHR>>>(feats);
    prep_w_kernel<<<(KNB * 2 * DIM * DIM) / NTHR, NTHR>>>(W1, W2);

    {
        dim3 cgrid(NBLK, 2, 1);
        conv_imma_kernel<<<cgrid, CTHR, SM_TOTAL>>>(nidx, nmask, b1, b2);
    }

    segreduce_kernel<<<(N_PTS + 511) / 512, 256>>>(segid);
    segmean_kernel<<<1, 1024>>>();

    finalize_kernel<<<N_PTS / FTILE, NTHR, smem_fin>>>(feats, segid, W3, b3, out);
}

// round 8
// speedup vs baseline: 3.9551x; 3.9551x over previous
#include <cuda_runtime.h>
#include <cuda_bf16.h>
#include <cstdint>

#define N_PTS 400000
#define DIM   128
#define KNB   27
#define NSEG  8
#define MTILE 128
#define CTHR  512
#define NTHR  256
#define NBLK  (N_PTS / MTILE)
#define FTILE 64

// ---------------- scratch (static device globals: allocation-free) ----------------
__device__ float g_out1[(size_t)N_PTS * DIM];
__device__ float g_out2[(size_t)N_PTS * DIM];
__device__ float g_segsum[NSEG * DIM];
__device__ float g_segmean[NSEG * DIM];
__device__ int   g_segcnt[NSEG];
__device__ __nv_bfloat16 g_fhi[(size_t)N_PTS * DIM];
__device__ __nv_bfloat16 g_flo[(size_t)N_PTS * DIM];
// W images: [k][conv][part(hi/lo)] 32KB tiles, SMEM-image (row-swizzled, ldmatrix-ready)
__device__ __nv_bfloat16 g_Wimg[(size_t)KNB * 2 * 2 * 16384];
// W3 image: [part(hi/lo)] 32KB tiles (128 rows x 256B each)
__device__ __nv_bfloat16 g_W3img[2 * 16384];

// ---------------- smem layout for conv kernel (bytes) ----------------
#define SM_MB   0          // mbars: W1H@0 W1L@8 W2H@16 W2L@24
#define SM_IDX  64
#define SM_MSK  (SM_IDX + MTILE * KNB * 4)      // 13888
#define SM_AHI  17408
#define SM_ALO  (SM_AHI + 32768)                // 50176
#define SM_W1H  (SM_ALO + 32768)                // 82944
#define SM_W1L  (SM_W1H + 32768)                // 115712
#define SM_W2H  (SM_W1L + 32768)                // 148480
#define SM_W2L  (SM_W2H + 32768)                // 181248
#define SM_TOTAL (SM_W2L + 32768)               // 214016

// ---------------- smem layout for finalize kernel (bytes) ----------------
#define FM_W3H 0                                // 32KB
#define FM_W3L 32768                            // 32KB
#define FM_AH  65536                            // 16KB (64 rows x 256B)
#define FM_AL  81920                            // 16KB
#define FM_RED 98304                            // 256 floats
#define FM_RM  (FM_RED + NTHR * 4)              // 64 floats
#define FM_TOT (FM_RM + FTILE * 4)              // 99584

__device__ __forceinline__ uint32_t smem_u32(const void* p) {
    return (uint32_t)__cvta_generic_to_shared(p);
}

// ---------------- PTX helpers (baseline sm_80/sm_90 features only) ----------------
#define MBAR_INIT(a, c) \
    asm volatile("mbarrier.init.shared.b64 [%0], %1;" :: "r"(a), "r"(c) : "memory")
#define MBAR_EXPECT_TX(a, b) \
    asm volatile("mbarrier.arrive.expect_tx.shared.b64 _, [%0], %1;" :: "r"(a), "r"(b) : "memory")
#define MBAR_WAIT(a, ph) do {                                                 \
    uint32_t _m = (a), _p = (ph), _d;                                         \
    asm volatile("{\n .reg .pred p;\n"                                        \
        " mbarrier.try_wait.parity.acquire.cta.shared::cta.b64 p, [%1], %2;\n"\
        " selp.b32 %0, 1, 0, p;\n}" : "=r"(_d) : "r"(_m), "r"(_p) : "memory");\
    if (!_d) {                                                                \
        asm volatile("{\n .reg .pred P1;\n"                                   \
        "W%=:\n mbarrier.try_wait.parity.acquire.cta.shared::cta.b64 P1, [%0], %1, 0x989680;\n" \
        " @P1 bra.uni D%=;\n bra.uni W%=;\nD%=:\n}" :: "r"(_m), "r"(_p) : "memory"); \
    } } while (0)

#define CP_COMMIT() asm volatile("cp.async.commit_group;" ::: "memory")
#define CP_WAIT(n)  asm volatile("cp.async.wait_group %0;" :: "n"(n) : "memory")

__device__ __forceinline__ void cp16z(uint32_t dst, const void* src, uint32_t srcsz) {
    asm volatile("cp.async.cg.shared.global [%0], [%1], 16, %2;"
                 :: "r"(dst), "l"(src), "r"(srcsz) : "memory");
}
__device__ __forceinline__ void bulk_g2s(uint32_t dst, const void* src,
                                         uint32_t bytes, uint32_t mbar) {
    asm volatile(
        "cp.async.bulk.shared::cluster.global.mbarrier::complete_tx::bytes "
        "[%0], [%1], %2, [%3];"
        :: "r"(dst), "l"(src), "r"(bytes), "r"(mbar) : "memory");
}
__device__ __forceinline__ void ldsm4(uint32_t* r, uint32_t addr) {
    asm volatile("ldmatrix.sync.aligned.m8n8.x4.shared.b16 {%0,%1,%2,%3}, [%4];"
        : "=r"(r[0]), "=r"(r[1]), "=r"(r[2]), "=r"(r[3]) : "r"(addr));
}
__device__ __forceinline__ void mma_bf16(float* c, const uint32_t* a, const uint32_t* b) {
    asm volatile("mma.sync.aligned.m16n8k16.row.col.f32.bf16.bf16.f32 "
        "{%0,%1,%2,%3}, {%4,%5,%6,%7}, {%8,%9}, {%0,%1,%2,%3};"
        : "+f"(c[0]), "+f"(c[1]), "+f"(c[2]), "+f"(c[3])
        : "r"(a[0]), "r"(a[1]), "r"(a[2]), "r"(a[3]), "r"(b[0]), "r"(b[1]));
}
__device__ __forceinline__ uint32_t packbf2(float lo, float hi) {
    uint32_t r;
    asm("cvt.rn.bf16x2.f32 %0, %1, %2;" : "=r"(r) : "f"(hi), "f"(lo));
    return r;
}

// ---------------- pre-pass: split feats into bf16 hi/lo ----------------
__global__ void split_feats_kernel(const float* __restrict__ feats) {
    const size_t i = ((size_t)blockIdx.x * NTHR + threadIdx.x) * 4;
    const float4 v = *reinterpret_cast<const float4*>(feats + i);
    const float hx = __bfloat162float(__float2bfloat16(v.x));
    const float hy = __bfloat162float(__float2bfloat16(v.y));
    const float hz = __bfloat162float(__float2bfloat16(v.z));
    const float hw = __bfloat162float(__float2bfloat16(v.w));
    uint2 hi, lo;
    hi.x = packbf2(v.x, v.y);       hi.y = packbf2(v.z, v.w);
    lo.x = packbf2(v.x - hx, v.y - hy);
    lo.y = packbf2(v.z - hz, v.w - hw);
    *reinterpret_cast<uint2*>(g_fhi + i) = hi;
    *reinterpret_cast<uint2*>(g_flo + i) = lo;
}

// ---------------- pre-pass: W -> transposed, split, SMEM-image layout ----------
// W image tile (32KB) = 128 n-rows x 256B; row n holds 128 bf16 over kdim d,
// 16B chunk c stored at chunk (c ^ (n&7))  [ldmatrix swizzle]
__global__ void prep_w_kernel(const float* __restrict__ W1, const float* __restrict__ W2) {
    const uint32_t t = blockIdx.x * NTHR + threadIdx.x;   // 27*2*128*128 threads
    const uint32_t d = t & 127;
    const uint32_t n = (t >> 7) & 127;
    const uint32_t conv = (t >> 14) & 1;
    const uint32_t k = t >> 15;
    const float w = (conv ? W2 : W1)[((size_t)k * DIM + d) * DIM + n];
    const float hf = __bfloat162float(__float2bfloat16(w));
    const uint32_t off = n * 256 + ((((d >> 3) ^ (n & 7)) << 4)) + (d & 7) * 2;
    const size_t tile = (size_t)((k * 2 + conv) * 2);
    g_Wimg[tile * 16384 + (off >> 1)]       = __float2bfloat16(w);
    g_Wimg[(tile + 1) * 16384 + (off >> 1)] = __float2bfloat16(w - hf);
}

// ---------------- pre-pass: W3 -> split hi/lo SMEM-image (32KB per part) ----------
__global__ void prep_w3_kernel(const float* __restrict__ W3) {
    const uint32_t t = blockIdx.x * NTHR + threadIdx.x;   // 128*128 threads
    const uint32_t n = t & 127;
    const uint32_t d = t >> 7;
    const float w = W3[(size_t)d * DIM + n];
    const float hf = __bfloat162float(__float2bfloat16(w));
    const uint32_t off = n * 256 + ((((d >> 3) ^ (n & 7)) << 4)) + (d & 7) * 2;
    g_W3img[off >> 1]          = __float2bfloat16(w);
    g_W3img[16384 + (off >> 1)] = __float2bfloat16(w - hf);
}

// ---------------- zero segment accumulators ----------------
__global__ void zero_seg_kernel() {
    int t = blockIdx.x * blockDim.x + threadIdx.x;
    if (t < NSEG * DIM) g_segsum[t] = 0.f;
    if (t < NSEG) g_segcnt[t] = 0;
}

// ---------------- A staging via cp.async zfill (512 threads, 32KB/part) ----------
__device__ __forceinline__ void stage_A_cp(uint32_t sb, uint32_t a_base,
                                           const __nv_bfloat16* fsrc,
                                           const int* idx_s,
                                           const unsigned char* msk_s, int k) {
    const int t = threadIdx.x;
    const int r = t >> 2;                  // row 0..127
    const int q = t & 3;                   // 4 chunks per thread
    const int id = idx_s[r * KNB + k];
    const uint32_t sz = msk_s[r * KNB + k] ? 16u : 0u;
    const char* src = reinterpret_cast<const char*>(fsrc + (size_t)id * DIM) + q * 64;
    const uint32_t drow = sb + a_base + (uint32_t)r * 256;
    const uint32_t x = (uint32_t)(r & 7);
#pragma unroll
    for (int c2 = 0; c2 < 4; c2++) {
        const uint32_t c = (uint32_t)(q * 4 + c2);
        cp16z(drow + ((c ^ x) << 4), src + c2 * 16, sz);
    }
}

// ---------------- MMA product groups ----------------
// warp tile 32(m) x 32(n); acc[i<2][j<4][4]
__device__ __forceinline__ void mma_group1(uint32_t sb, uint32_t a_base, uint32_t w_base,
                                           float acc[2][4][4],
                                           uint32_t a_row, uint32_t b_row,
                                           uint32_t ahalf, uint32_t bhalf, uint32_t xr) {
#pragma unroll
    for (uint32_t kc = 0; kc < 8; kc++) {
        const uint32_t ach = ((2 * kc + ahalf) ^ xr) << 4;
        const uint32_t bch = ((2 * kc + bhalf) ^ xr) << 4;
        uint32_t a0[4], a1[4], wb[8];
        ldsm4(a0, sb + a_base + a_row + ach);
        ldsm4(a1, sb + a_base + a_row + 4096 + ach);
        ldsm4(&wb[0], sb + w_base + b_row + bch);
        ldsm4(&wb[4], sb + w_base + b_row + 4096 + bch);
#pragma unroll
        for (int j = 0; j < 4; j++) {
            mma_bf16(acc[0][j], a0, &wb[j * 2]);
            mma_bf16(acc[1][j], a1, &wb[j * 2]);
        }
    }
}
__device__ __forceinline__ void mma_group2(uint32_t sb, uint32_t a_base,
                                           uint32_t wh_base, uint32_t wl_base,
                                           float acc[2][4][4],
                                           uint32_t a_row, uint32_t b_row,
                                           uint32_t ahalf, uint32_t bhalf, uint32_t xr) {
#pragma unroll
    for (uint32_t kc = 0; kc < 8; kc++) {
        const uint32_t ach = ((2 * kc + ahalf) ^ xr) << 4;
        const uint32_t bch = ((2 * kc + bhalf) ^ xr) << 4;
        uint32_t a0[4], a1[4], wb[8];
        ldsm4(a0, sb + a_base + a_row + ach);
        ldsm4(a1, sb + a_base + a_row + 4096 + ach);
        ldsm4(&wb[0], sb + wh_base + b_row + bch);
        ldsm4(&wb[4], sb + wh_base + b_row + 4096 + bch);
#pragma unroll
        for (int j = 0; j < 4; j++) {
            mma_bf16(acc[0][j], a0, &wb[j * 2]);
            mma_bf16(acc[1][j], a1, &wb[j * 2]);
        }
        ldsm4(&wb[0], sb + wl_base + b_row + bch);
        ldsm4(&wb[4], sb + wl_base + b_row + 4096 + bch);
#pragma unroll
        for (int j = 0; j < 4; j++) {
            mma_bf16(acc[0][j], a0, &wb[j * 2]);
            mma_bf16(acc[1][j], a1, &wb[j * 2]);
        }
    }
}

// ---------------- conv kernel: phased single-buffered pipeline (R5, proven) -------
__global__ void __launch_bounds__(CTHR, 1)
conv_mma_kernel(const int* __restrict__ nidx, const int* __restrict__ nmask,
                const float* __restrict__ b1, const float* __restrict__ b2) {
    extern __shared__ char smem[];
    const uint32_t sb = smem_u32(smem);
    const int t = threadIdx.x;
    const int lane = t & 31;
    const int wid = t >> 5;
    const int wm = wid >> 2;        // 0..3 : 32-row band
    const int wn = wid & 3;         // 0..3 : 32-col band
    const int nbase = blockIdx.x * MTILE;

    int* idx_s = reinterpret_cast<int*>(smem + SM_IDX);
    unsigned char* msk_s = reinterpret_cast<unsigned char*>(smem + SM_MSK);

    for (int i = t; i < MTILE * KNB; i += CTHR) {
        idx_s[i] = nidx[(size_t)nbase * KNB + i];
        msk_s[i] = (unsigned char)(nmask[(size_t)nbase * KNB + i] != 0);
    }

    const char* wimg = reinterpret_cast<const char*>(g_Wimg);
    if (t == 0) {
        MBAR_INIT(sb + SM_MB, 1);       // W1H
        MBAR_INIT(sb + SM_MB + 8, 1);   // W1L
        MBAR_INIT(sb + SM_MB + 16, 1);  // W2H
        MBAR_INIT(sb + SM_MB + 24, 1);  // W2L
        MBAR_EXPECT_TX(sb + SM_MB, 32768);
        bulk_g2s(sb + SM_W1H, wimg + 0 * 32768, 32768, sb + SM_MB);
        MBAR_EXPECT_TX(sb + SM_MB + 8, 32768);
        bulk_g2s(sb + SM_W1L, wimg + 1 * 32768, 32768, sb + SM_MB + 8);
        MBAR_EXPECT_TX(sb + SM_MB + 16, 32768);
        bulk_g2s(sb + SM_W2H, wimg + 2 * 32768, 32768, sb + SM_MB + 16);
        MBAR_EXPECT_TX(sb + SM_MB + 24, 32768);
        bulk_g2s(sb + SM_W2L, wimg + 3 * 32768, 32768, sb + SM_MB + 24);
    }
    __syncthreads();   // idx_s/msk_s + mbar init visible
    stage_A_cp(sb, SM_ALO, g_flo, idx_s, msk_s, 0);
    CP_COMMIT();
    stage_A_cp(sb, SM_AHI, g_fhi, idx_s, msk_s, 0);
    CP_COMMIT();

    // per-thread ldmatrix address components
    const uint32_t a_row = (uint32_t)(wm * 32 + (lane & 15)) * 256;
    const uint32_t b_row = (uint32_t)(wn * 32 + ((lane >> 4) << 3) + (lane & 7)) * 256;
    const uint32_t xr = (uint32_t)(lane & 7);
    const uint32_t ahalf = (uint32_t)(lane >> 4);
    const uint32_t bhalf = (uint32_t)((lane >> 3) & 1);

    float acc[2][2][4][4];
#pragma unroll
    for (int c = 0; c < 2; c++)
#pragma unroll
        for (int i = 0; i < 2; i++)
#pragma unroll
            for (int j = 0; j < 4; j++)
#pragma unroll
                for (int q = 0; q < 4; q++) acc[c][i][j][q] = 0.f;

#pragma unroll 1
    for (int k = 0; k < KNB; k++) {
        const uint32_t ph = (uint32_t)(k & 1);
        const bool nxt = (k < KNB - 1);

        // ---- g1: Alo x W1hi ----
        CP_WAIT(1);                // Alo[k] done (own)
        __syncthreads();           // B1: Alo visible to all
        MBAR_WAIT(sb + SM_MB, ph); // W1H[k]
        mma_group1(sb, SM_ALO, SM_W1H, acc[0], a_row, b_row, ahalf, bhalf, xr);

        // ---- g23: Ahi x (W1hi, W1lo) ----
        CP_WAIT(0);                // Ahi[k] done (own)
        __syncthreads();           // B2: Ahi visible
        MBAR_WAIT(sb + SM_MB + 8, ph); // W1L[k]
        mma_group2(sb, SM_AHI, SM_W1H, SM_W1L, acc[0], a_row, b_row, ahalf, bhalf, xr);
        __syncthreads();           // B3: W1H/W1L dead
        if (nxt && t == 0) {
            const size_t tb = (size_t)(k + 1) * 4 * 32768;
            MBAR_EXPECT_TX(sb + SM_MB, 32768);
            bulk_g2s(sb + SM_W1H, wimg + tb, 32768, sb + SM_MB);
            MBAR_EXPECT_TX(sb + SM_MB + 8, 32768);
            bulk_g2s(sb + SM_W1L, wimg + tb + 32768, 32768, sb + SM_MB + 8);
        }

        // ---- g4: Alo x W2hi ----
        MBAR_WAIT(sb + SM_MB + 16, ph); // W2H[k]
        mma_group1(sb, SM_ALO, SM_W2H, acc[1], a_row, b_row, ahalf, bhalf, xr);
        __syncthreads();           // B4: Alo dead
        if (nxt) stage_A_cp(sb, SM_ALO, g_flo, idx_s, msk_s, k + 1);
        CP_COMMIT();

        // ---- g56: Ahi x (W2hi, W2lo) ----
        MBAR_WAIT(sb + SM_MB + 24, ph); // W2L[k]
        mma_group2(sb, SM_AHI, SM_W2H, SM_W2L, acc[1], a_row, b_row, ahalf, bhalf, xr);
        __syncthreads();           // B5: W2H/W2L + Ahi dead
        if (nxt && t == 0) {
            const size_t tb = (size_t)(k + 1) * 4 * 32768;
            MBAR_EXPECT_TX(sb + SM_MB + 16, 32768);
            bulk_g2s(sb + SM_W2H, wimg + tb + 65536, 32768, sb + SM_MB + 16);
            MBAR_EXPECT_TX(sb + SM_MB + 24, 32768);
            bulk_g2s(sb + SM_W2L, wimg + tb + 98304, 32768, sb + SM_MB + 24);
        }
        if (nxt) stage_A_cp(sb, SM_AHI, g_fhi, idx_s, msk_s, k + 1);
        CP_COMMIT();
    }

    // epilogue: +bias, relu, store fp32
    const int g = lane >> 2, tig = lane & 3;
#pragma unroll
    for (int c = 0; c < 2; c++) {
        float* outp = c ? g_out2 : g_out1;
        const float* bias = c ? b2 : b1;
#pragma unroll
        for (int j = 0; j < 4; j++) {
            const int col = wn * 32 + j * 8 + tig * 2;
            const float2 bv = *reinterpret_cast<const float2*>(bias + col);
#pragma unroll
            for (int i = 0; i < 2; i++) {
                const int row0 = nbase + wm * 32 + i * 16 + g;
                float2 v0, v1;
                v0.x = fmaxf(acc[c][i][j][0] + bv.x, 0.f);
                v0.y = fmaxf(acc[c][i][j][1] + bv.y, 0.f);
                v1.x = fmaxf(acc[c][i][j][2] + bv.x, 0.f);
                v1.y = fmaxf(acc[c][i][j][3] + bv.y, 0.f);
                *reinterpret_cast<float2*>(outp + (size_t)row0 * DIM + col) = v0;
                *reinterpret_cast<float2*>(outp + (size_t)(row0 + 8) * DIM + col) = v1;
            }
        }
    }
}

// ---------------- segment sums of out2 (+counts); segment_ids sorted ----------
__global__ void segreduce_kernel(const int* __restrict__ segid) {
    const int RPB = 512, HALF = 256;
    const int c = threadIdx.x & 127;
    const int h = threadIdx.x >> 7;
    const int r0 = blockIdx.x * RPB + h * HALF;
    if (r0 >= N_PTS) return;
    const int r1 = min(r0 + HALF, N_PTS);

    float sum = 0.f;
    int cur = -1;
    for (int r = r0; r < r1; r++) {
        const int s = segid[r];
        if (s != cur) {
            if (cur >= 0) atomicAdd(&g_segsum[cur * DIM + c], sum);
            cur = s; sum = 0.f;
        }
        sum += g_out2[(size_t)r * DIM + c];
    }
    if (cur >= 0) atomicAdd(&g_segsum[cur * DIM + c], sum);

    if (c == 0) {
        int cnt = 0; cur = -1;
        for (int r = r0; r < r1; r++) {
            const int s = segid[r];
            if (s != cur) {
                if (cur >= 0) atomicAdd(&g_segcnt[cur], cnt);
                cur = s; cnt = 0;
            }
            cnt++;
        }
        if (cur >= 0) atomicAdd(&g_segcnt[cur], cnt);
    }
}

__global__ void segmean_kernel() {
    const int t = threadIdx.x;  // 1024 threads
    const int s = t >> 7;
    const float cnt = fmaxf((float)g_segcnt[s], 1.0f);
    g_segmean[t] = g_segsum[t] / cnt;
}

// ---------------- finalize (tensorized): enc, mid, mid@W3, relu(feats - relu(.)) --
__global__ void __launch_bounds__(NTHR, 2)
finalize_mma_kernel(const float* __restrict__ feats, const int* __restrict__ segid,
                    const float* __restrict__ b3, float* __restrict__ out) {
    extern __shared__ char smem[];
    const uint32_t sb = smem_u32(smem);
    const int t = threadIdx.x;
    const int lane = t & 31;
    const int wid = t >> 5;
    const int nbase = blockIdx.x * FTILE;

    // stage W3 hi/lo images (64KB, linear copy)
    {
        const uint4* src = reinterpret_cast<const uint4*>(g_W3img);
        uint4* dst = reinterpret_cast<uint4*>(smem + FM_W3H);
#pragma unroll
        for (int i = 0; i < 16; i++) dst[t + i * NTHR] = src[t + i * NTHR];
    }

    float* red  = reinterpret_cast<float*>(smem + FM_RED);
    float* rm1s = reinterpret_cast<float*>(smem + FM_RM);

    const int gpt = t & 63, gseg = t >> 6;
    const int n = nbase + gpt;

    const float4* o1p = reinterpret_cast<const float4*>(g_out1 + (size_t)n * DIM) + gseg * 8;
    const float4* o2p = reinterpret_cast<const float4*>(g_out2 + (size_t)n * DIM) + gseg * 8;

    float4 v1[8];
    float psum = 0.f;
#pragma unroll
    for (int q = 0; q < 8; q++) {
        v1[q] = o1p[q];
        psum += v1[q].x + v1[q].y + v1[q].z + v1[q].w;
    }
    red[t] = psum;
    __syncthreads();
    if (t < FTILE)
        rm1s[t] = (red[t] + red[t + 64] + red[t + 128] + red[t + 192]) * (1.0f / 128.0f);
    __syncthreads();

    const float rm = rm1s[gpt];
    const int sg = segid[n];
    const float4* smn = reinterpret_cast<const float4*>(g_segmean + sg * DIM) + gseg * 8;

    // mid = enc + out1 + out2; split to bf16 hi/lo; STS to swizzled A images
    const uint32_t xg = (uint32_t)(gpt & 7);
#pragma unroll
    for (int cc = 0; cc < 4; cc++) {
        float m[8];
#pragma unroll
        for (int h = 0; h < 2; h++) {
            const int q = cc * 2 + h;
            const float4 b = o2p[q];
            const float4 mm = smn[q];
            m[h * 4 + 0] = sqrtf(fmaf(rm, mm.x, 1e-12f)) + v1[q].x + b.x;
            m[h * 4 + 1] = sqrtf(fmaf(rm, mm.y, 1e-12f)) + v1[q].y + b.y;
            m[h * 4 + 2] = sqrtf(fmaf(rm, mm.z, 1e-12f)) + v1[q].z + b.z;
            m[h * 4 + 3] = sqrtf(fmaf(rm, mm.w, 1e-12f)) + v1[q].w + b.w;
        }
        uint4 hi, lo;
        hi.x = packbf2(m[0], m[1]); hi.y = packbf2(m[2], m[3]);
        hi.z = packbf2(m[4], m[5]); hi.w = packbf2(m[6], m[7]);
        float r[8];
#pragma unroll
        for (int e = 0; e < 8; e++)
            r[e] = m[e] - __bfloat162float(__float2bfloat16(m[e]));
        lo.x = packbf2(r[0], r[1]); lo.y = packbf2(r[2], r[3]);
        lo.z = packbf2(r[4], r[5]); lo.w = packbf2(r[6], r[7]);
        const uint32_t c = (uint32_t)(gseg * 4 + cc);
        const uint32_t off = (uint32_t)gpt * 256 + ((c ^ xg) << 4);
        *reinterpret_cast<uint4*>(smem + FM_AH + off) = hi;
        *reinterpret_cast<uint4*>(smem + FM_AL + off) = lo;
    }
    __syncthreads();

    // mma: 8 warps, tile 64(m) x 128(n); warp tile 32x32
    const int wm = wid >> 2;        // 0..1
    const int wn = wid & 3;         // 0..3
    const uint32_t a_row = (uint32_t)(wm * 32 + (lane & 15)) * 256;
    const uint32_t b_row = (uint32_t)(wn * 32 + ((lane >> 4) << 3) + (lane & 7)) * 256;
    const uint32_t xr = (uint32_t)(lane & 7);
    const uint32_t ahalf = (uint32_t)(lane >> 4);
    const uint32_t bhalf = (uint32_t)((lane >> 3) & 1);

    float acc[2][4][4];
#pragma unroll
    for (int i = 0; i < 2; i++)
#pragma unroll
        for (int j = 0; j < 4; j++)
#pragma unroll
            for (int q = 0; q < 4; q++) acc[i][j][q] = 0.f;

    mma_group1(sb, FM_AL, FM_W3H, acc, a_row, b_row, ahalf, bhalf, xr);
    mma_group2(sb, FM_AH, FM_W3H, FM_W3L, acc, a_row, b_row, ahalf, bhalf, xr);

    // epilogue: +b3, relu, feats - , relu, store
    const int g = lane >> 2, tig = lane & 3;
#pragma unroll
    for (int j = 0; j < 4; j++) {
        const int col = wn * 32 + j * 8 + tig * 2;
        const float2 bv = *reinterpret_cast<const float2*>(b3 + col);
#pragma unroll
        for (int i = 0; i < 2; i++) {
            const int row0 = nbase + wm * 32 + i * 16 + g;
            const float2 f0 = *reinterpret_cast<const float2*>(feats + (size_t)row0 * DIM + col);
            const float2 f1 = *reinterpret_cast<const float2*>(feats + (size_t)(row0 + 8) * DIM + col);
            float2 v0, v1r;
            v0.x  = fmaxf(f0.x - fmaxf(acc[i][j][0] + bv.x, 0.f), 0.f);
            v0.y  = fmaxf(f0.y - fmaxf(acc[i][j][1] + bv.y, 0.f), 0.f);
            v1r.x = fmaxf(f1.x - fmaxf(acc[i][j][2] + bv.x, 0.f), 0.f);
            v1r.y = fmaxf(f1.y - fmaxf(acc[i][j][3] + bv.y, 0.f), 0.f);
            *reinterpret_cast<float2*>(out + (size_t)row0 * DIM + col) = v0;
            *reinterpret_cast<float2*>(out + (size_t)(row0 + 8) * DIM + col) = v1r;
        }
    }
}

// ---------------- launch ----------------
extern "C" void kernel_launch(void* const* d_in, const int* in_sizes, int n_in,
                              void* d_out, int out_size) {
    const float* feats = (const float*)d_in[0];
    const int* nidx = (const int*)d_in[1];
    const int* nmask = (const int*)d_in[2];   // bool materialized as int32
    const int* segid = (const int*)d_in[3];
    const int o = (n_in >= 11) ? 1 : 0;
    const float* W1 = (const float*)d_in[4 + o];
    const float* b1 = (const float*)d_in[5 + o];
    const float* W2 = (const float*)d_in[6 + o];
    const float* b2 = (const float*)d_in[7 + o];
    const float* W3 = (const float*)d_in[8 + o];
    const float* b3 = (const float*)d_in[9 + o];
    float* out = (float*)d_out;

    cudaFuncSetAttribute(conv_mma_kernel, cudaFuncAttributeMaxDynamicSharedMemorySize,
                         SM_TOTAL);
    cudaFuncSetAttribute(finalize_mma_kernel, cudaFuncAttributeMaxDynamicSharedMemorySize,
                         FM_TOT);

    zero_seg_kernel<<<1, 1024>>>();
    split_feats_kernel<<<(N_PTS * DIM) / (NTHR * 4), NTHR>>>(feats);
    prep_w_kernel<<<(KNB * 2 * DIM * DIM) / NTHR, NTHR>>>(W1, W2);
    prep_w3_kernel<<<(DIM * DIM) / NTHR, NTHR>>>(W3);

    conv_mma_kernel<<<NBLK, CTHR, SM_TOTAL>>>(nidx, nmask, b1, b2);

    segreduce_kernel<<<(N_PTS + 511) / 512, 256>>>(segid);
    segmean_kernel<<<1, 1024>>>();

    finalize_mma_kernel<<<N_PTS / FTILE, NTHR, FM_TOT>>>(feats, segid, b3, out);
}

// round 9
// speedup vs baseline: 4.1163x; 1.0408x over previous
#include <cuda_runtime.h>
#include <cuda_bf16.h>
#include <cstdint>

#define N_PTS 400000
#define DIM   128
#define KNB   27
#define NSEG  8
#define MTILE 128
#define CTHR  512
#define NTHR  256
#define NBLK  (N_PTS / MTILE)
#define FTILE 64

// ---------------- scratch (static device globals: allocation-free) ----------------
__device__ float g_out1[(size_t)N_PTS * DIM];
__device__ float g_out2[(size_t)N_PTS * DIM];
__device__ float g_segsum[NSEG * DIM];
__device__ float g_segmean[NSEG * DIM];
__device__ int   g_segcnt[NSEG];
__device__ __nv_bfloat16 g_fhi[(size_t)N_PTS * DIM];
__device__ __nv_bfloat16 g_flo[(size_t)N_PTS * DIM];
// W images: [k][part(hi/lo)][conv] 32KB tiles -> hi pair contiguous, lo pair contiguous
__device__ __nv_bfloat16 g_Wimg[(size_t)KNB * 2 * 2 * 16384];
// W3 image: [part(hi/lo)] 32KB tiles (128 rows x 256B each)
__device__ __nv_bfloat16 g_W3img[2 * 16384];

// ---------------- smem layout for conv kernel (bytes) ----------------
#define SM_MB   0          // mbars: WH@0 WL@8
#define SM_IDX  64
#define SM_MSK  (SM_IDX + MTILE * KNB * 4)      // 13888
#define SM_AHI  17408
#define SM_ALO  (SM_AHI + 32768)                // 50176
#define SM_WH   (SM_ALO + 32768)                // 82944  (W1h, W2h@+32768)
#define SM_WL   (SM_WH + 65536)                 // 148480 (W1l, W2l@+32768)
#define SM_TOTAL (SM_WL + 65536)                // 214016

// ---------------- smem layout for finalize kernel (bytes) ----------------
#define FM_W3H 0                                // 32KB
#define FM_W3L 32768                            // 32KB
#define FM_AH  65536                            // 16KB (64 rows x 256B)
#define FM_AL  81920                            // 16KB
#define FM_RED 98304                            // 256 floats
#define FM_RM  (FM_RED + NTHR * 4)              // 64 floats
#define FM_TOT (FM_RM + FTILE * 4)              // 99584

__device__ __forceinline__ uint32_t smem_u32(const void* p) {
    return (uint32_t)__cvta_generic_to_shared(p);
}

// ---------------- PTX helpers (baseline sm_80/sm_90 features only) ----------------
#define MBAR_INIT(a, c) \
    asm volatile("mbarrier.init.shared.b64 [%0], %1;" :: "r"(a), "r"(c) : "memory")
#define MBAR_EXPECT_TX(a, b) \
    asm volatile("mbarrier.arrive.expect_tx.shared.b64 _, [%0], %1;" :: "r"(a), "r"(b) : "memory")
#define MBAR_WAIT(a, ph) do {                                                 \
    uint32_t _m = (a), _p = (ph), _d;                                         \
    asm volatile("{\n .reg .pred p;\n"                                        \
        " mbarrier.try_wait.parity.acquire.cta.shared::cta.b64 p, [%1], %2;\n"\
        " selp.b32 %0, 1, 0, p;\n}" : "=r"(_d) : "r"(_m), "r"(_p) : "memory");\
    if (!_d) {                                                                \
        asm volatile("{\n .reg .pred P1;\n"                                   \
        "W%=:\n mbarrier.try_wait.parity.acquire.cta.shared::cta.b64 P1, [%0], %1, 0x989680;\n" \
        " @P1 bra.uni D%=;\n bra.uni W%=;\nD%=:\n}" :: "r"(_m), "r"(_p) : "memory"); \
    } } while (0)

#define CP_COMMIT() asm volatile("cp.async.commit_group;" ::: "memory")
#define CP_WAIT(n)  asm volatile("cp.async.wait_group %0;" :: "n"(n) : "memory")

__device__ __forceinline__ void cp16z(uint32_t dst, const void* src, uint32_t srcsz) {
    asm volatile("cp.async.cg.shared.global [%0], [%1], 16, %2;"
                 :: "r"(dst), "l"(src), "r"(srcsz) : "memory");
}
__device__ __forceinline__ void bulk_g2s(uint32_t dst, const void* src,
                                         uint32_t bytes, uint32_t mbar) {
    asm volatile(
        "cp.async.bulk.shared::cluster.global.mbarrier::complete_tx::bytes "
        "[%0], [%1], %2, [%3];"
        :: "r"(dst), "l"(src), "r"(bytes), "r"(mbar) : "memory");
}
__device__ __forceinline__ void ldsm4(uint32_t* r, uint32_t addr) {
    asm volatile("ldmatrix.sync.aligned.m8n8.x4.shared.b16 {%0,%1,%2,%3}, [%4];"
        : "=r"(r[0]), "=r"(r[1]), "=r"(r[2]), "=r"(r[3]) : "r"(addr));
}
__device__ __forceinline__ void mma_bf16(float* c, const uint32_t* a, const uint32_t* b) {
    asm volatile("mma.sync.aligned.m16n8k16.row.col.f32.bf16.bf16.f32 "
        "{%0,%1,%2,%3}, {%4,%5,%6,%7}, {%8,%9}, {%0,%1,%2,%3};"
        : "+f"(c[0]), "+f"(c[1]), "+f"(c[2]), "+f"(c[3])
        : "r"(a[0]), "r"(a[1]), "r"(a[2]), "r"(a[3]), "r"(b[0]), "r"(b[1]));
}
__device__ __forceinline__ uint32_t packbf2(float lo, float hi) {
    uint32_t r;
    asm("cvt.rn.bf16x2.f32 %0, %1, %2;" : "=r"(r) : "f"(hi), "f"(lo));
    return r;
}

// ---------------- pre-pass: split feats into bf16 hi/lo ----------------
__global__ void split_feats_kernel(const float* __restrict__ feats) {
    const size_t i = ((size_t)blockIdx.x * NTHR + threadIdx.x) * 4;
    const float4 v = *reinterpret_cast<const float4*>(feats + i);
    const float hx = __bfloat162float(__float2bfloat16(v.x));
    const float hy = __bfloat162float(__float2bfloat16(v.y));
    const float hz = __bfloat162float(__float2bfloat16(v.z));
    const float hw = __bfloat162float(__float2bfloat16(v.w));
    uint2 hi, lo;
    hi.x = packbf2(v.x, v.y);       hi.y = packbf2(v.z, v.w);
    lo.x = packbf2(v.x - hx, v.y - hy);
    lo.y = packbf2(v.z - hz, v.w - hw);
    *reinterpret_cast<uint2*>(g_fhi + i) = hi;
    *reinterpret_cast<uint2*>(g_flo + i) = lo;
}

// ---------------- pre-pass: W -> transposed, split, SMEM-image layout ----------
// tile index = k*4 + part*2 + conv  ->  per-k block: [W1h, W2h, W1l, W2l]
__global__ void prep_w_kernel(const float* __restrict__ W1, const float* __restrict__ W2) {
    const uint32_t t = blockIdx.x * NTHR + threadIdx.x;   // 27*2*128*128 threads
    const uint32_t d = t & 127;
    const uint32_t n = (t >> 7) & 127;
    const uint32_t conv = (t >> 14) & 1;
    const uint32_t k = t >> 15;
    const float w = (conv ? W2 : W1)[((size_t)k * DIM + d) * DIM + n];
    const float hf = __bfloat162float(__float2bfloat16(w));
    const uint32_t off = n * 256 + ((((d >> 3) ^ (n & 7)) << 4)) + (d & 7) * 2;
    const size_t khi = (size_t)(k * 4 + conv);        // hi slot
    const size_t klo = (size_t)(k * 4 + 2 + conv);    // lo slot
    g_Wimg[khi * 16384 + (off >> 1)] = __float2bfloat16(w);
    g_Wimg[klo * 16384 + (off >> 1)] = __float2bfloat16(w - hf);
}

// ---------------- pre-pass: W3 -> split hi/lo SMEM-image (32KB per part) ----------
__global__ void prep_w3_kernel(const float* __restrict__ W3) {
    const uint32_t t = blockIdx.x * NTHR + threadIdx.x;   // 128*128 threads
    const uint32_t n = t & 127;
    const uint32_t d = t >> 7;
    const float w = W3[(size_t)d * DIM + n];
    const float hf = __bfloat162float(__float2bfloat16(w));
    const uint32_t off = n * 256 + ((((d >> 3) ^ (n & 7)) << 4)) + (d & 7) * 2;
    g_W3img[off >> 1]          = __float2bfloat16(w);
    g_W3img[16384 + (off >> 1)] = __float2bfloat16(w - hf);
}

// ---------------- zero segment accumulators ----------------
__global__ void zero_seg_kernel() {
    int t = blockIdx.x * blockDim.x + threadIdx.x;
    if (t < NSEG * DIM) g_segsum[t] = 0.f;
    if (t < NSEG) g_segcnt[t] = 0;
}

// ---------------- A staging via cp.async zfill (512 threads, 32KB/part) ----------
__device__ __forceinline__ void stage_A_cp(uint32_t sb, uint32_t a_base,
                                           const __nv_bfloat16* fsrc,
                                           const int* idx_s,
                                           const unsigned char* msk_s, int k) {
    const int t = threadIdx.x;
    const int r = t >> 2;                  // row 0..127
    const int q = t & 3;                   // 4 chunks per thread
    const int id = idx_s[r * KNB + k];
    const uint32_t sz = msk_s[r * KNB + k] ? 16u : 0u;
    const char* src = reinterpret_cast<const char*>(fsrc + (size_t)id * DIM) + q * 64;
    const uint32_t drow = sb + a_base + (uint32_t)r * 256;
    const uint32_t x = (uint32_t)(r & 7);
#pragma unroll
    for (int c2 = 0; c2 < 4; c2++) {
        const uint32_t c = (uint32_t)(q * 4 + c2);
        cp16z(drow + ((c ^ x) << 4), src + c2 * 16, sz);
    }
}

// ---------------- MMA: one A-part x both convs' W tiles (w2 at +32768) ----------
// per kc: 6 ldsm, 16 MMA.  acc[conv][i<2][j<4][4]
__device__ __forceinline__ void mma_dual(uint32_t sb, uint32_t a_base, uint32_t w_base,
                                         float acc[2][2][4][4],
                                         uint32_t a_row, uint32_t b_row,
                                         uint32_t ahalf, uint32_t bhalf, uint32_t xr) {
#pragma unroll
    for (uint32_t kc = 0; kc < 8; kc++) {
        const uint32_t ach = ((2 * kc + ahalf) ^ xr) << 4;
        const uint32_t bch = ((2 * kc + bhalf) ^ xr) << 4;
        uint32_t a0[4], a1[4], w1[8], w2[8];
        ldsm4(a0, sb + a_base + a_row + ach);
        ldsm4(a1, sb + a_base + a_row + 4096 + ach);
        ldsm4(&w1[0], sb + w_base + b_row + bch);
        ldsm4(&w1[4], sb + w_base + b_row + 4096 + bch);
        ldsm4(&w2[0], sb + w_base + 32768 + b_row + bch);
        ldsm4(&w2[4], sb + w_base + 32768 + b_row + 4096 + bch);
#pragma unroll
        for (int j = 0; j < 4; j++) {
            mma_bf16(acc[0][0][j], a0, &w1[j * 2]);
            mma_bf16(acc[0][1][j], a1, &w1[j * 2]);
            mma_bf16(acc[1][0][j], a0, &w2[j * 2]);
            mma_bf16(acc[1][1][j], a1, &w2[j * 2]);
        }
    }
}

// ---------------- MMA product groups (used by finalize) ----------------
__device__ __forceinline__ void mma_group1(uint32_t sb, uint32_t a_base, uint32_t w_base,
                                           float acc[2][4][4],
                                           uint32_t a_row, uint32_t b_row,
                                           uint32_t ahalf, uint32_t bhalf, uint32_t xr) {
#pragma unroll
    for (uint32_t kc = 0; kc < 8; kc++) {
        const uint32_t ach = ((2 * kc + ahalf) ^ xr) << 4;
        const uint32_t bch = ((2 * kc + bhalf) ^ xr) << 4;
        uint32_t a0[4], a1[4], wb[8];
        ldsm4(a0, sb + a_base + a_row + ach);
        ldsm4(a1, sb + a_base + a_row + 4096 + ach);
        ldsm4(&wb[0], sb + w_base + b_row + bch);
        ldsm4(&wb[4], sb + w_base + b_row + 4096 + bch);
#pragma unroll
        for (int j = 0; j < 4; j++) {
            mma_bf16(acc[0][j], a0, &wb[j * 2]);
            mma_bf16(acc[1][j], a1, &wb[j * 2]);
        }
    }
}
__device__ __forceinline__ void mma_group2(uint32_t sb, uint32_t a_base,
                                           uint32_t wh_base, uint32_t wl_base,
                                           float acc[2][4][4],
                                           uint32_t a_row, uint32_t b_row,
                                           uint32_t ahalf, uint32_t bhalf, uint32_t xr) {
#pragma unroll
    for (uint32_t kc = 0; kc < 8; kc++) {
        const uint32_t ach = ((2 * kc + ahalf) ^ xr) << 4;
        const uint32_t bch = ((2 * kc + bhalf) ^ xr) << 4;
        uint32_t a0[4], a1[4], wb[8];
        ldsm4(a0, sb + a_base + a_row + ach);
        ldsm4(a1, sb + a_base + a_row + 4096 + ach);
        ldsm4(&wb[0], sb + wh_base + b_row + bch);
        ldsm4(&wb[4], sb + wh_base + b_row + 4096 + bch);
#pragma unroll
        for (int j = 0; j < 4; j++) {
            mma_bf16(acc[0][j], a0, &wb[j * 2]);
            mma_bf16(acc[1][j], a1, &wb[j * 2]);
        }
        ldsm4(&wb[0], sb + wl_base + b_row + bch);
        ldsm4(&wb[4], sb + wl_base + b_row + 4096 + bch);
#pragma unroll
        for (int j = 0; j < 4; j++) {
            mma_bf16(acc[0][j], a0, &wb[j * 2]);
            mma_bf16(acc[1][j], a1, &wb[j * 2]);
        }
    }
}

// ---------------- conv kernel: 3-phase dual-conv pipeline ----------------
__global__ void __launch_bounds__(CTHR, 1)
conv_mma_kernel(const int* __restrict__ nidx, const int* __restrict__ nmask,
                const float* __restrict__ b1, const float* __restrict__ b2) {
    extern __shared__ char smem[];
    const uint32_t sb = smem_u32(smem);
    const int t = threadIdx.x;
    const int lane = t & 31;
    const int wid = t >> 5;
    const int wm = wid >> 2;        // 0..3 : 32-row band
    const int wn = wid & 3;         // 0..3 : 32-col band
    const int nbase = blockIdx.x * MTILE;

    int* idx_s = reinterpret_cast<int*>(smem + SM_IDX);
    unsigned char* msk_s = reinterpret_cast<unsigned char*>(smem + SM_MSK);

    for (int i = t; i < MTILE * KNB; i += CTHR) {
        idx_s[i] = nidx[(size_t)nbase * KNB + i];
        msk_s[i] = (unsigned char)(nmask[(size_t)nbase * KNB + i] != 0);
    }

    const char* wimg = reinterpret_cast<const char*>(g_Wimg);
    if (t == 0) {
        MBAR_INIT(sb + SM_MB, 1);       // WH (W1h+W2h)
        MBAR_INIT(sb + SM_MB + 8, 1);   // WL (W1l+W2l)
        MBAR_EXPECT_TX(sb + SM_MB, 65536);
        bulk_g2s(sb + SM_WH, wimg + 0, 65536, sb + SM_MB);
        MBAR_EXPECT_TX(sb + SM_MB + 8, 65536);
        bulk_g2s(sb + SM_WL, wimg + 65536, 65536, sb + SM_MB + 8);
    }
    __syncthreads();   // idx_s/msk_s + mbar init visible
    stage_A_cp(sb, SM_ALO, g_flo, idx_s, msk_s, 0);
    CP_COMMIT();
    stage_A_cp(sb, SM_AHI, g_fhi, idx_s, msk_s, 0);
    CP_COMMIT();

    // per-thread ldmatrix address components
    const uint32_t a_row = (uint32_t)(wm * 32 + (lane & 15)) * 256;
    const uint32_t b_row = (uint32_t)(wn * 32 + ((lane >> 4) << 3) + (lane & 7)) * 256;
    const uint32_t xr = (uint32_t)(lane & 7);
    const uint32_t ahalf = (uint32_t)(lane >> 4);
    const uint32_t bhalf = (uint32_t)((lane >> 3) & 1);

    float acc[2][2][4][4];
#pragma unroll
    for (int c = 0; c < 2; c++)
#pragma unroll
        for (int i = 0; i < 2; i++)
#pragma unroll
            for (int j = 0; j < 4; j++)
#pragma unroll
                for (int q = 0; q < 4; q++) acc[c][i][j][q] = 0.f;

#pragma unroll 1
    for (int k = 0; k < KNB; k++) {
        const uint32_t ph = (uint32_t)(k & 1);
        const bool nxt = (k < KNB - 1);

        // ---- phase A: Alo x (W1h, W2h) ----
        CP_WAIT(1);                // Alo[k] done (own); Ahi[k] may fly
        __syncthreads();           // Alo visible to all
        MBAR_WAIT(sb + SM_MB, ph); // WH[k]
        mma_dual(sb, SM_ALO, SM_WH, acc, a_row, b_row, ahalf, bhalf, xr);

        // ---- phase B: Ahi x (W1h, W2h) ----
        CP_WAIT(0);                // Ahi[k] done (own)
        __syncthreads();           // Alo dead CTA-wide + Ahi visible
        if (nxt) stage_A_cp(sb, SM_ALO, g_flo, idx_s, msk_s, k + 1);
        CP_COMMIT();
        mma_dual(sb, SM_AHI, SM_WH, acc, a_row, b_row, ahalf, bhalf, xr);

        // ---- phase C: Ahi x (W1l, W2l) ----
        __syncthreads();           // WH dead
        if (nxt && t == 0) {
            const size_t tb = (size_t)(k + 1) * 131072;
            MBAR_EXPECT_TX(sb + SM_MB, 65536);
            bulk_g2s(sb + SM_WH, wimg + tb, 65536, sb + SM_MB);
        }
        MBAR_WAIT(sb + SM_MB + 8, ph); // WL[k]
        mma_dual(sb, SM_AHI, SM_WL, acc, a_row, b_row, ahalf, bhalf, xr);

        __syncthreads();           // WL + Ahi dead
        if (nxt && t == 0) {
            const size_t tb = (size_t)(k + 1) * 131072;
            MBAR_EXPECT_TX(sb + SM_MB + 8, 65536);
            bulk_g2s(sb + SM_WL, wimg + tb + 65536, 65536, sb + SM_MB + 8);
        }
        if (nxt) stage_A_cp(sb, SM_AHI, g_fhi, idx_s, msk_s, k + 1);
        CP_COMMIT();
    }

    // epilogue: +bias, relu, store fp32
    const int g = lane >> 2, tig = lane & 3;
#pragma unroll
    for (int c = 0; c < 2; c++) {
        float* outp = c ? g_out2 : g_out1;
        const float* bias = c ? b2 : b1;
#pragma unroll
        for (int j = 0; j < 4; j++) {
            const int col = wn * 32 + j * 8 + tig * 2;
            const float2 bv = *reinterpret_cast<const float2*>(bias + col);
#pragma unroll
            for (int i = 0; i < 2; i++) {
                const int row0 = nbase + wm * 32 + i * 16 + g;
                float2 v0, v1;
                v0.x = fmaxf(acc[c][i][j][0] + bv.x, 0.f);
                v0.y = fmaxf(acc[c][i][j][1] + bv.y, 0.f);
                v1.x = fmaxf(acc[c][i][j][2] + bv.x, 0.f);
                v1.y = fmaxf(acc[c][i][j][3] + bv.y, 0.f);
                *reinterpret_cast<float2*>(outp + (size_t)row0 * DIM + col) = v0;
                *reinterpret_cast<float2*>(outp + (size_t)(row0 + 8) * DIM + col) = v1;
            }
        }
    }
}

// ---------------- segment sums of out2 (+counts); segment_ids sorted ----------
__global__ void segreduce_kernel(const int* __restrict__ segid) {
    const int RPB = 512, HALF = 256;
    const int c = threadIdx.x & 127;
    const int h = threadIdx.x >> 7;
    const int r0 = blockIdx.x * RPB + h * HALF;
    if (r0 >= N_PTS) return;
    const int r1 = min(r0 + HALF, N_PTS);

    float sum = 0.f;
    int cur = -1;
    for (int r = r0; r < r1; r++) {
        const int s = segid[r];
        if (s != cur) {
            if (cur >= 0) atomicAdd(&g_segsum[cur * DIM + c], sum);
            cur = s; sum = 0.f;
        }
        sum += g_out2[(size_t)r * DIM + c];
    }
    if (cur >= 0) atomicAdd(&g_segsum[cur * DIM + c], sum);

    if (c == 0) {
        int cnt = 0; cur = -1;
        for (int r = r0; r < r1; r++) {
            const int s = segid[r];
            if (s != cur) {
                if (cur >= 0) atomicAdd(&g_segcnt[cur], cnt);
                cur = s; cnt = 0;
            }
            cnt++;
        }
        if (cur >= 0) atomicAdd(&g_segcnt[cur], cnt);
    }
}

__global__ void segmean_kernel() {
    const int t = threadIdx.x;  // 1024 threads
    const int s = t >> 7;
    const float cnt = fmaxf((float)g_segcnt[s], 1.0f);
    g_segmean[t] = g_segsum[t] / cnt;
}

// ---------------- finalize (tensorized): enc, mid, mid@W3, relu(feats - relu(.)) --
__global__ void __launch_bounds__(NTHR, 2)
finalize_mma_kernel(const float* __restrict__ feats, const int* __restrict__ segid,
                    const float* __restrict__ b3, float* __restrict__ out) {
    extern __shared__ char smem[];
    const uint32_t sb = smem_u32(smem);
    const int t = threadIdx.x;
    const int lane = t & 31;
    const int wid = t >> 5;
    const int nbase = blockIdx.x * FTILE;

    // stage W3 hi/lo images (64KB, linear copy)
    {
        const uint4* src = reinterpret_cast<const uint4*>(g_W3img);
        uint4* dst = reinterpret_cast<uint4*>(smem + FM_W3H);
#pragma unroll
        for (int i = 0; i < 16; i++) dst[t + i * NTHR] = src[t + i * NTHR];
    }

    float* red  = reinterpret_cast<float*>(smem + FM_RED);
    float* rm1s = reinterpret_cast<float*>(smem + FM_RM);

    const int gpt = t & 63, gseg = t >> 6;
    const int n = nbase + gpt;

    const float4* o1p = reinterpret_cast<const float4*>(g_out1 + (size_t)n * DIM) + gseg * 8;
    const float4* o2p = reinterpret_cast<const float4*>(g_out2 + (size_t)n * DIM) + gseg * 8;

    float4 v1[8];
    float psum = 0.f;
#pragma unroll
    for (int q = 0; q < 8; q++) {
        v1[q] = o1p[q];
        psum += v1[q].x + v1[q].y + v1[q].z + v1[q].w;
    }
    red[t] = psum;
    __syncthreads();
    if (t < FTILE)
        rm1s[t] = (red[t] + red[t + 64] + red[t + 128] + red[t + 192]) * (1.0f / 128.0f);
    __syncthreads();

    const float rm = rm1s[gpt];
    const int sg = segid[n];
    const float4* smn = reinterpret_cast<const float4*>(g_segmean + sg * DIM) + gseg * 8;

    // mid = enc + out1 + out2; split to bf16 hi/lo; STS to swizzled A images
    const uint32_t xg = (uint32_t)(gpt & 7);
#pragma unroll
    for (int cc = 0; cc < 4; cc++) {
        float m[8];
#pragma unroll
        for (int h = 0; h < 2; h++) {
            const int q = cc * 2 + h;
            const float4 b = o2p[q];
            const float4 mm = smn[q];
            m[h * 4 + 0] = sqrtf(fmaf(rm, mm.x, 1e-12f)) + v1[q].x + b.x;
            m[h * 4 + 1] = sqrtf(fmaf(rm, mm.y, 1e-12f)) + v1[q].y + b.y;
            m[h * 4 + 2] = sqrtf(fmaf(rm, mm.z, 1e-12f)) + v1[q].z + b.z;
            m[h * 4 + 3] = sqrtf(fmaf(rm, mm.w, 1e-12f)) + v1[q].w + b.w;
        }
        uint4 hi, lo;
        hi.x = packbf2(m[0], m[1]); hi.y = packbf2(m[2], m[3]);
        hi.z = packbf2(m[4], m[5]); hi.w = packbf2(m[6], m[7]);
        float r[8];
#pragma unroll
        for (int e = 0; e < 8; e++)
            r[e] = m[e] - __bfloat162float(__float2bfloat16(m[e]));
        lo.x = packbf2(r[0], r[1]); lo.y = packbf2(r[2], r[3]);
        lo.z = packbf2(r[4], r[5]); lo.w = packbf2(r[6], r[7]);
        const uint32_t c = (uint32_t)(gseg * 4 + cc);
        const uint32_t off = (uint32_t)gpt * 256 + ((c ^ xg) << 4);
        *reinterpret_cast<uint4*>(smem + FM_AH + off) = hi;
        *reinterpret_cast<uint4*>(smem + FM_AL + off) = lo;
    }
    __syncthreads();

    // mma: 8 warps, tile 64(m) x 128(n); warp tile 32x32
    const int wm = wid >> 2;        // 0..1
    const int wn = wid & 3;         // 0..3
    const uint32_t a_row = (uint32_t)(wm * 32 + (lane & 15)) * 256;
    const uint32_t b_row = (uint32_t)(wn * 32 + ((lane >> 4) << 3) + (lane & 7)) * 256;
    const uint32_t xr = (uint32_t)(lane & 7);
    const uint32_t ahalf = (uint32_t)(lane >> 4);
    const uint32_t bhalf = (uint32_t)((lane >> 3) & 1);

    float acc[2][4][4];
#pragma unroll
    for (int i = 0; i < 2; i++)
#pragma unroll
        for (int j = 0; j < 4; j++)
#pragma unroll
            for (int q = 0; q < 4; q++) acc[i][j][q] = 0.f;

    mma_group1(sb, FM_AL, FM_W3H, acc, a_row, b_row, ahalf, bhalf, xr);
    mma_group2(sb, FM_AH, FM_W3H, FM_W3L, acc, a_row, b_row, ahalf, bhalf, xr);

    // epilogue: +b3, relu, feats - , relu, store
    const int g = lane >> 2, tig = lane & 3;
#pragma unroll
    for (int j = 0; j < 4; j++) {
        const int col = wn * 32 + j * 8 + tig * 2;
        const float2 bv = *reinterpret_cast<const float2*>(b3 + col);
#pragma unroll
        for (int i = 0; i < 2; i++) {
            const int row0 = nbase + wm * 32 + i * 16 + g;
            const float2 f0 = *reinterpret_cast<const float2*>(feats + (size_t)row0 * DIM + col);
            const float2 f1 = *reinterpret_cast<const float2*>(feats + (size_t)(row0 + 8) * DIM + col);
            float2 v0, v1r;
            v0.x  = fmaxf(f0.x - fmaxf(acc[i][j][0] + bv.x, 0.f), 0.f);
            v0.y  = fmaxf(f0.y - fmaxf(acc[i][j][1] + bv.y, 0.f), 0.f);
            v1r.x = fmaxf(f1.x - fmaxf(acc[i][j][2] + bv.x, 0.f), 0.f);
            v1r.y = fmaxf(f1.y - fmaxf(acc[i][j][3] + bv.y, 0.f), 0.f);
            *reinterpret_cast<float2*>(out + (size_t)row0 * DIM + col) = v0;
            *reinterpret_cast<float2*>(out + (size_t)(row0 + 8) * DIM + col) = v1r;
        }
    }
}

// ---------------- launch ----------------
extern "C" void kernel_launch(void* const* d_in, const int* in_sizes, int n_in,
                              void* d_out, int out_size) {
    const float* feats = (const float*)d_in[0];
    const int* nidx = (const int*)d_in[1];
    const int* nmask = (const int*)d_in[2];   // bool materialized as int32
    const int* segid = (const int*)d_in[3];
    const int o = (n_in >= 11) ? 1 : 0;
    const float* W1 = (const float*)d_in[4 + o];
    const float* b1 = (const float*)d_in[5 + o];
    const float* W2 = (const float*)d_in[6 + o];
    const float* b2 = (const float*)d_in[7 + o];
    const float* W3 = (const float*)d_in[8 + o];
    const float* b3 = (const float*)d_in[9 + o];
    float* out = (float*)d_out;

    cudaFuncSetAttribute(conv_mma_kernel, cudaFuncAttributeMaxDynamicSharedMemorySize,
                         SM_TOTAL);
    cudaFuncSetAttribute(finalize_mma_kernel, cudaFuncAttributeMaxDynamicSharedMemorySize,
                         FM_TOT);

    zero_seg_kernel<<<1, 1024>>>();
    split_feats_kernel<<<(N_PTS * DIM) / (NTHR * 4), NTHR>>>(feats);
    prep_w_kernel<<<(KNB * 2 * DIM * DIM) / NTHR, NTHR>>>(W1, W2);
    prep_w3_kernel<<<(DIM * DIM) / NTHR, NTHR>>>(W3);

    conv_mma_kernel<<<NBLK, CTHR, SM_TOTAL>>>(nidx, nmask, b1, b2);

    segreduce_kernel<<<(N_PTS + 511) / 512, 256>>>(segid);
    segmean_kernel<<<1, 1024>>>();

    finalize_mma_kernel<<<N_PTS / FTILE, NTHR, FM_TOT>>>(feats, segid, b3, out);
}